// round 12
// baseline (speedup 1.0000x reference)
#include <cuda_runtime.h>
#include <cuda_fp16.h>
#include <stdint.h>

#define NT 4
#define P0 100
#define P1C 100
#define P2C 100
#define NSLICE (NT * P1C * P2C)     // 40000
#define HALF_SLICE (NSLICE / 2)     // 20000
#define BKT_CAP 64
#define HALF_NNZ 262144             // nnz/2 for the expected shape

// W12 scratch, per (t,i1,i2) slice as TWO mma.m16n8k16 A-fragments. 41 MB.
__device__ __align__(16) __half g_W12[(size_t)NSLICE * 512];
// c0 as fp16 B-fragments per (t,i0) slice. 204.8KB.
__device__ uint4 g_c0f[(size_t)NT * P0 * 32];
// Slice buckets: counts + member lists (value = n | i0<<19).
__device__ int g_cnt[40960];
__device__ int g_bkt[(size_t)NSLICE * BKT_CAP];
// Per-lookup rows for ONE half (tables pair), fp16: 32 uints = 128B. 33.5MB.
__device__ unsigned g_rows[(size_t)HALF_NNZ * 32];

// r = {hi:lo} packed fp16x2 (low element = first arg)
__device__ __forceinline__ unsigned pack_h2(float lo, float hi) {
    unsigned r;
    asm("cvt.rn.f16x2.f32 %0, %1, %2;" : "=r"(r) : "f"(hi), "f"(lo));
    return r;
}

// ---------------------------------------------------------------------------
// Kernel 1 (fused): blocks 0..399 = (t,i1) tensor-core W12 GEMM;
// blocks 400..403 build c0 B-fragments; blocks 404..443 zero g_cnt.
// ---------------------------------------------------------------------------
__global__ __launch_bounds__(256) void tt_precompute_kernel(
        const float* __restrict__ c1g, const float* __restrict__ c2g,
        const float* __restrict__ c0g) {
    int b = blockIdx.x;
    int tid = threadIdx.x;

    if (b >= NT * P1C + NT) {                   // ---- zero g_cnt ----
        int base = (b - NT * P1C - NT) * 1024 + tid * 4;
        #pragma unroll
        for (int i = 0; i < 4; i++)
            if (base + i < 40960) g_cnt[base + i] = 0;
        return;
    }
    if (b >= NT * P1C) {                        // ---- c0 fragment blocks ----
        int tt = b - NT * P1C;
        for (int task = tid; task < P0 * 32; task += 256) {
            int sl = task >> 5, lane = task & 31;
            int g = lane >> 2, j = lane & 3;
            uint4 v = make_uint4(0u, 0u, 0u, 0u);
            if (g < 4) {
                const float* row = c0g + ((size_t)(tt * P0 + sl)) * 128 + g * 32 + 2 * j;
                float2 p0 = *(const float2*)(row);
                float2 p1 = *(const float2*)(row + 8);
                float2 p2 = *(const float2*)(row + 16);
                float2 p3 = *(const float2*)(row + 24);
                v.x = pack_h2(p0.x, p0.y);
                v.y = pack_h2(p1.x, p1.y);
                v.z = pack_h2(p2.x, p2.y);
                v.w = pack_h2(p3.x, p3.y);
            }
            g_c0f[(size_t)(tt * P0 + sl) * 32 + lane] = v;
        }
        return;
    }

    __shared__ uint4 smA[1600];   // A-frags (c2): [mt 25][ks 2][lane 32]
    __shared__ uint4 smB[512];    // B-frags (c1): [nt 16][lane 32]

    int t = b / P1C, i1 = b - t * P1C;

    const float* c2tab = c2g + (size_t)t * P2C * 128;
    for (int tau = tid; tau < 1600; tau += 256) {
        int mt = tau >> 6, ks = (tau >> 5) & 1, lane = tau & 31;
        int g = lane >> 2, tj = lane & 3;
        int i2a = 4 * mt + (g >> 2), q2 = g & 3;
        int kb = 16 * ks + 2 * tj;
        const float* pa = c2tab + i2a * 128 + q2;
        const float* pb = pa + 2 * 128;
        uint4 v;
        v.x = pack_h2(pa[kb * 4],       pa[(kb + 1) * 4]);
        v.y = pack_h2(pb[kb * 4],       pb[(kb + 1) * 4]);
        v.z = pack_h2(pa[(kb + 8) * 4], pa[(kb + 9) * 4]);
        v.w = pack_h2(pb[(kb + 8) * 4], pb[(kb + 9) * 4]);
        smA[tau] = v;
    }

    const float* c1 = c1g + (size_t)(t * P1C + i1) * 4096;
    for (int tau = tid; tau < 512; tau += 256) {
        int nt = tau >> 5, lane = tau & 31;
        int g = lane >> 2, tj = lane & 3;
        int q1 = nt >> 2, r1 = 8 * (nt & 3) + g;
        const float* row = c1 + (r1 * 4 + q1) * 32;
        uint4 v;
        v.x = pack_h2(row[2 * tj],      row[2 * tj + 1]);
        v.y = pack_h2(row[2 * tj + 8],  row[2 * tj + 9]);
        v.z = pack_h2(row[2 * tj + 16], row[2 * tj + 17]);
        v.w = pack_h2(row[2 * tj + 24], row[2 * tj + 25]);
        smB[tau] = v;
    }
    __syncthreads();

    int w = tid >> 5, lane = tid & 31;
    int g3 = (lane >> 2) & 3, tj = lane & 3, ghi = lane >> 4;
    char* Wb = (char*)g_W12 + (size_t)(t * P1C + i1) * P2C * 1024;

    for (int tau = w; tau < 100; tau += 8) {
        int mt = tau >> 2, qd = tau & 3;
        int nt0 = 2 * qd, f = qd & 1, q1b = qd >> 1;
        uint4 A0 = smA[mt * 64 + lane];
        uint4 A1 = smA[mt * 64 + 32 + lane];
        unsigned pa[4], pb[4];
        const int nts[4] = {nt0, nt0 + 8, nt0 + 1, nt0 + 9};
        #pragma unroll
        for (int s = 0; s < 4; s++) {
            uint4 Bv = smB[nts[s] * 32 + lane];
            float d0 = 0.f, d1 = 0.f, d2 = 0.f, d3 = 0.f;
            asm volatile(
                "mma.sync.aligned.m16n8k16.row.col.f32.f16.f16.f32 "
                "{%0,%1,%2,%3}, {%4,%5,%6,%7}, {%8,%9}, {%0,%1,%2,%3};"
                : "+f"(d0), "+f"(d1), "+f"(d2), "+f"(d3)
                : "r"(A0.x), "r"(A0.y), "r"(A0.z), "r"(A0.w),
                  "r"(Bv.x), "r"(Bv.y));
            asm volatile(
                "mma.sync.aligned.m16n8k16.row.col.f32.f16.f16.f32 "
                "{%0,%1,%2,%3}, {%4,%5,%6,%7}, {%8,%9}, {%0,%1,%2,%3};"
                : "+f"(d0), "+f"(d1), "+f"(d2), "+f"(d3)
                : "r"(A1.x), "r"(A1.y), "r"(A1.z), "r"(A1.w),
                  "r"(Bv.z), "r"(Bv.w));
            pa[s] = pack_h2(d0, d1);
            pb[s] = pack_h2(d2, d3);
        }
        size_t off = (size_t)(4 * mt + ghi) * 1024 + f * 512
                   + ((q1b * 4 + g3) * 4 + tj) * 16;
        *(uint4*)(Wb + off)        = make_uint4(pa[0], pa[1], pa[2], pa[3]);
        *(uint4*)(Wb + off + 2048) = make_uint4(pb[0], pb[1], pb[2], pb[3]);
    }
}

// ---------------------------------------------------------------------------
// Kernel 2: bucket lookups by slice. value = n | (i0 << 19).
// ---------------------------------------------------------------------------
__global__ void tt_scatter_kernel(const int* __restrict__ indices,
                                  int nnz, int nnz_per_table) {
    int n = blockIdx.x * blockDim.x + threadIdx.x;
    if (n >= nnz) return;
    int idx = indices[n];
    int i0  = idx / 10000;
    int rem = idx - i0 * 10000;
    int t   = n / nnz_per_table;
    int key = t * 10000 + rem;
    int p = atomicAdd(&g_cnt[key], 1);
    if (p < BKT_CAP)
        g_bkt[(size_t)key * BKT_CAP + p] = n | (i0 << 19);
}

// ---------------------------------------------------------------------------
// Kernel 3: materialize rows for one table-pair half. One warp per slice:
// W12 slice loaded ONCE into registers; per member: c0 frag + 2 HMMA + 128B
// row write at LOCAL index (rows buffer reused across halves -> L2-resident).
// ---------------------------------------------------------------------------
__global__ __launch_bounds__(256) void tt_materialize_kernel(int half,
                                                             int half_nnz) {
    int k = half * HALF_SLICE
          + blockIdx.x * (blockDim.x >> 5) + (threadIdx.x >> 5);
    if (k >= (half + 1) * HALF_SLICE) return;
    int lane = threadIdx.x & 31;
    int g = lane >> 2, j = lane & 3;

    int cnt = g_cnt[k];
    if (cnt > BKT_CAP) cnt = BKT_CAP;
    if (cnt == 0) return;

    int t = k / 10000;
    const uint4* wb = (const uint4*)g_W12 + (size_t)k * 64;
    const uint4* Cf = g_c0f + (size_t)t * P0 * 32;
    const int* bkt = g_bkt + (size_t)k * BKT_CAP;
    int nbase = half * half_nnz;

    uint4 A0 = wb[lane];
    uint4 A1 = wb[32 + lane];

    for (int c = 0; c < cnt; c++) {
        int v  = bkt[c];
        int n  = (v & 0x7FFFF) - nbase;        // local row index
        int i0 = v >> 19;
        uint4 Bf = Cf[i0 * 32 + lane];
        float d0 = 0.f, d1 = 0.f, d2 = 0.f, d3 = 0.f;
        asm volatile(
            "mma.sync.aligned.m16n8k16.row.col.f32.f16.f16.f32 "
            "{%0,%1,%2,%3}, {%4,%5,%6,%7}, {%8,%9}, {%0,%1,%2,%3};"
            : "+f"(d0), "+f"(d1), "+f"(d2), "+f"(d3)
            : "r"(A0.x), "r"(A0.y), "r"(A0.z), "r"(A0.w),
              "r"(Bf.x), "r"(Bf.y));
        asm volatile(
            "mma.sync.aligned.m16n8k16.row.col.f32.f16.f16.f32 "
            "{%0,%1,%2,%3}, {%4,%5,%6,%7}, {%8,%9}, {%0,%1,%2,%3};"
            : "+f"(d0), "+f"(d1), "+f"(d2), "+f"(d3)
            : "r"(A1.x), "r"(A1.y), "r"(A1.z), "r"(A1.w),
              "r"(Bf.z), "r"(Bf.w));
        if (j < 2) {
            unsigned* rp = g_rows + (size_t)n * 32;
            rp[g * 2 + j]       = pack_h2(d0, d1);
            rp[(g + 8) * 2 + j] = pack_h2(d2, d3);
        }
    }
}

// ---------------------------------------------------------------------------
// Kernel 4: pool one half's bags. One warp per bag; 16 contiguous 128B rows
// streamed from L2-resident g_rows; fp32 accumulation per lane slot.
// ---------------------------------------------------------------------------
__global__ void tt_pool_kernel(const int* __restrict__ offsets,
                               float* __restrict__ out,
                               int half, int half_B, int half_nnz) {
    int wbag = (int)((blockIdx.x * (size_t)blockDim.x + threadIdx.x) >> 5);
    if (wbag >= half_B) return;
    int bag = half * half_B + wbag;
    int l = threadIdx.x & 31;
    int m = l >> 1, j = l & 1;

    int nbase = half * half_nnz;
    int s = offsets[bag] - nbase, e = offsets[bag + 1] - nbase;
    float sx = 0.f, sy = 0.f;
    for (int n = s; n < e; n++) {
        __half2 h = *(const __half2*)(g_rows + (size_t)n * 32 + l);
        float2 f = __half22float2(h);
        sx += f.x;
        sy += f.y;
    }
    float* ob = out + (size_t)bag * 64;
    ob[(2 * j) * 16 + m]     = sx;
    ob[(2 * j + 1) * 16 + m] = sy;
}

// ---------------------------------------------------------------------------
extern "C" void kernel_launch(void* const* d_in, const int* in_sizes, int n_in,
                              void* d_out, int out_size) {
    const int* indices = (const int*)d_in[0];
    const int* offsets = (const int*)d_in[1];
    const float* c0 = (const float*)d_in[2];
    const float* c1 = (const float*)d_in[3];
    const float* c2 = (const float*)d_in[4];

    int nnz = in_sizes[0];
    int B = in_sizes[1] - 1;
    int nnz_per_table = nnz / NT;
    int half_nnz = nnz / 2;
    int half_B = B / 2;

    tt_precompute_kernel<<<NT * P1C + NT + 40, 256>>>(c1, c2, c0);
    tt_scatter_kernel<<<(nnz + 255) / 256, 256>>>(indices, nnz, nnz_per_table);

    int mat_blocks = (HALF_SLICE + 7) / 8;
    int pool_blocks = (half_B + 7) / 8;
    for (int h = 0; h < 2; h++) {
        tt_materialize_kernel<<<mat_blocks, 256>>>(h, half_nnz);
        tt_pool_kernel<<<pool_blocks, 256>>>(offsets, (float*)d_out,
                                             h, half_B, half_nnz);
    }
}

// round 14
// speedup vs baseline: 1.1509x; 1.1509x over previous
#include <cuda_runtime.h>
#include <cuda_fp16.h>
#include <stdint.h>

#define NT 4
#define P0 100
#define P1C 100
#define P2C 100
#define NSLICE (NT * P1C * P2C)     // 40000
#define BKT_CAP 64
#define MAX_NNZ 524288

// W12 scratch, per (t,i1,i2) slice as TWO mma.m16n8k16 A-fragments. 41 MB.
__device__ __align__(16) __half g_W12[(size_t)NSLICE * 512];
// c0 as fp16 B-fragments per (t,i0) slice. 204.8KB.
__device__ uint4 g_c0f[(size_t)NT * P0 * 32];
// Slice buckets: counts + member lists (value = n | i0<<19).
__device__ int g_cnt[40960];
__device__ int g_bkt[(size_t)NSLICE * BKT_CAP];
// Per-lookup reconstructed rows, fp16, 32 uints = 128B each. 67MB.
// Kept L2-resident by demoting all competing streams to .cs (evict-first).
__device__ unsigned g_rows[(size_t)MAX_NNZ * 32];

// r = {hi:lo} packed fp16x2 (low element = first arg)
__device__ __forceinline__ unsigned pack_h2(float lo, float hi) {
    unsigned r;
    asm("cvt.rn.f16x2.f32 %0, %1, %2;" : "=r"(r) : "f"(hi), "f"(lo));
    return r;
}

// ---------------------------------------------------------------------------
// Kernel 1 (fused): blocks 0..399 = (t,i1) tensor-core W12 GEMM;
// blocks 400..403 build c0 B-fragments; blocks 404..443 zero g_cnt.
// ---------------------------------------------------------------------------
__global__ __launch_bounds__(256) void tt_precompute_kernel(
        const float* __restrict__ c1g, const float* __restrict__ c2g,
        const float* __restrict__ c0g) {
    int b = blockIdx.x;
    int tid = threadIdx.x;

    if (b >= NT * P1C + NT) {                   // ---- zero g_cnt ----
        int base = (b - NT * P1C - NT) * 1024 + tid * 4;
        #pragma unroll
        for (int i = 0; i < 4; i++)
            if (base + i < 40960) g_cnt[base + i] = 0;
        return;
    }
    if (b >= NT * P1C) {                        // ---- c0 fragment blocks ----
        int tt = b - NT * P1C;
        for (int task = tid; task < P0 * 32; task += 256) {
            int sl = task >> 5, lane = task & 31;
            int g = lane >> 2, j = lane & 3;
            uint4 v = make_uint4(0u, 0u, 0u, 0u);
            if (g < 4) {
                const float* row = c0g + ((size_t)(tt * P0 + sl)) * 128 + g * 32 + 2 * j;
                float2 p0 = *(const float2*)(row);
                float2 p1 = *(const float2*)(row + 8);
                float2 p2 = *(const float2*)(row + 16);
                float2 p3 = *(const float2*)(row + 24);
                v.x = pack_h2(p0.x, p0.y);
                v.y = pack_h2(p1.x, p1.y);
                v.z = pack_h2(p2.x, p2.y);
                v.w = pack_h2(p3.x, p3.y);
            }
            g_c0f[(size_t)(tt * P0 + sl) * 32 + lane] = v;
        }
        return;
    }

    __shared__ uint4 smA[1600];   // A-frags (c2): [mt 25][ks 2][lane 32]
    __shared__ uint4 smB[512];    // B-frags (c1): [nt 16][lane 32]

    int t = b / P1C, i1 = b - t * P1C;

    const float* c2tab = c2g + (size_t)t * P2C * 128;
    for (int tau = tid; tau < 1600; tau += 256) {
        int mt = tau >> 6, ks = (tau >> 5) & 1, lane = tau & 31;
        int g = lane >> 2, tj = lane & 3;
        int i2a = 4 * mt + (g >> 2), q2 = g & 3;
        int kb = 16 * ks + 2 * tj;
        const float* pa = c2tab + i2a * 128 + q2;
        const float* pb = pa + 2 * 128;
        uint4 v;
        v.x = pack_h2(pa[kb * 4],       pa[(kb + 1) * 4]);
        v.y = pack_h2(pb[kb * 4],       pb[(kb + 1) * 4]);
        v.z = pack_h2(pa[(kb + 8) * 4], pa[(kb + 9) * 4]);
        v.w = pack_h2(pb[(kb + 8) * 4], pb[(kb + 9) * 4]);
        smA[tau] = v;
    }

    const float* c1 = c1g + (size_t)(t * P1C + i1) * 4096;
    for (int tau = tid; tau < 512; tau += 256) {
        int nt = tau >> 5, lane = tau & 31;
        int g = lane >> 2, tj = lane & 3;
        int q1 = nt >> 2, r1 = 8 * (nt & 3) + g;
        const float* row = c1 + (r1 * 4 + q1) * 32;
        uint4 v;
        v.x = pack_h2(row[2 * tj],      row[2 * tj + 1]);
        v.y = pack_h2(row[2 * tj + 8],  row[2 * tj + 9]);
        v.z = pack_h2(row[2 * tj + 16], row[2 * tj + 17]);
        v.w = pack_h2(row[2 * tj + 24], row[2 * tj + 25]);
        smB[tau] = v;
    }
    __syncthreads();

    int w = tid >> 5, lane = tid & 31;
    int g3 = (lane >> 2) & 3, tj = lane & 3, ghi = lane >> 4;
    char* Wb = (char*)g_W12 + (size_t)(t * P1C + i1) * P2C * 1024;

    for (int tau = w; tau < 100; tau += 8) {
        int mt = tau >> 2, qd = tau & 3;
        int nt0 = 2 * qd, f = qd & 1, q1b = qd >> 1;
        uint4 A0 = smA[mt * 64 + lane];
        uint4 A1 = smA[mt * 64 + 32 + lane];
        unsigned pa[4], pb[4];
        const int nts[4] = {nt0, nt0 + 8, nt0 + 1, nt0 + 9};
        #pragma unroll
        for (int s = 0; s < 4; s++) {
            uint4 Bv = smB[nts[s] * 32 + lane];
            float d0 = 0.f, d1 = 0.f, d2 = 0.f, d3 = 0.f;
            asm volatile(
                "mma.sync.aligned.m16n8k16.row.col.f32.f16.f16.f32 "
                "{%0,%1,%2,%3}, {%4,%5,%6,%7}, {%8,%9}, {%0,%1,%2,%3};"
                : "+f"(d0), "+f"(d1), "+f"(d2), "+f"(d3)
                : "r"(A0.x), "r"(A0.y), "r"(A0.z), "r"(A0.w),
                  "r"(Bv.x), "r"(Bv.y));
            asm volatile(
                "mma.sync.aligned.m16n8k16.row.col.f32.f16.f16.f32 "
                "{%0,%1,%2,%3}, {%4,%5,%6,%7}, {%8,%9}, {%0,%1,%2,%3};"
                : "+f"(d0), "+f"(d1), "+f"(d2), "+f"(d3)
                : "r"(A1.x), "r"(A1.y), "r"(A1.z), "r"(A1.w),
                  "r"(Bv.z), "r"(Bv.w));
            pa[s] = pack_h2(d0, d1);
            pb[s] = pack_h2(d2, d3);
        }
        size_t off = (size_t)(4 * mt + ghi) * 1024 + f * 512
                   + ((q1b * 4 + g3) * 4 + tj) * 16;
        *(uint4*)(Wb + off)        = make_uint4(pa[0], pa[1], pa[2], pa[3]);
        *(uint4*)(Wb + off + 2048) = make_uint4(pb[0], pb[1], pb[2], pb[3]);
    }
}

// ---------------------------------------------------------------------------
// Kernel 2: bucket lookups by slice. value = n | (i0 << 19).
// ---------------------------------------------------------------------------
__global__ void tt_scatter_kernel(const int* __restrict__ indices,
                                  int nnz, int nnz_per_table) {
    int n = blockIdx.x * blockDim.x + threadIdx.x;
    if (n >= nnz) return;
    int idx = __ldcs(indices + n);              // read-once stream
    int i0  = idx / 10000;
    int rem = idx - i0 * 10000;
    int t   = n / nnz_per_table;
    int key = t * 10000 + rem;
    int p = atomicAdd(&g_cnt[key], 1);
    if (p < BKT_CAP)
        g_bkt[(size_t)key * BKT_CAP + p] = n | (i0 << 19);
}

// ---------------------------------------------------------------------------
// Kernel 3: materialize rows. One warp per slice. W12 slice streamed in ONCE
// (.cs, evict-first) into registers; per member: c0 frag + 2 HMMA + 128B row
// write (default policy -> stays in L2 for the pool kernel).
// ---------------------------------------------------------------------------
__global__ __launch_bounds__(256) void tt_materialize_kernel() {
    int k = blockIdx.x * (blockDim.x >> 5) + (threadIdx.x >> 5);
    if (k >= NSLICE) return;
    int lane = threadIdx.x & 31;
    int g = lane >> 2, j = lane & 3;

    int cnt = __ldcs(&g_cnt[k]);
    if (cnt > BKT_CAP) cnt = BKT_CAP;
    if (cnt == 0) return;

    int t = k / 10000;
    const uint4* wb = (const uint4*)g_W12 + (size_t)k * 64;
    const uint4* Cf = g_c0f + (size_t)t * P0 * 32;
    const int* bkt = g_bkt + (size_t)k * BKT_CAP;

    uint4 A0 = __ldcs(wb + lane);        // read-once: streaming hint
    uint4 A1 = __ldcs(wb + 32 + lane);

    for (int c = 0; c < cnt; c++) {
        int v  = __ldcs(bkt + c);
        int n  = v & 0x7FFFF;
        int i0 = v >> 19;
        uint4 Bf = Cf[i0 * 32 + lane];   // hot, default caching
        float d0 = 0.f, d1 = 0.f, d2 = 0.f, d3 = 0.f;
        asm volatile(
            "mma.sync.aligned.m16n8k16.row.col.f32.f16.f16.f32 "
            "{%0,%1,%2,%3}, {%4,%5,%6,%7}, {%8,%9}, {%0,%1,%2,%3};"
            : "+f"(d0), "+f"(d1), "+f"(d2), "+f"(d3)
            : "r"(A0.x), "r"(A0.y), "r"(A0.z), "r"(A0.w),
              "r"(Bf.x), "r"(Bf.y));
        asm volatile(
            "mma.sync.aligned.m16n8k16.row.col.f32.f16.f16.f32 "
            "{%0,%1,%2,%3}, {%4,%5,%6,%7}, {%8,%9}, {%0,%1,%2,%3};"
            : "+f"(d0), "+f"(d1), "+f"(d2), "+f"(d3)
            : "r"(A1.x), "r"(A1.y), "r"(A1.z), "r"(A1.w),
              "r"(Bf.z), "r"(Bf.w));
        if (j < 2) {
            unsigned* rp = g_rows + (size_t)n * 32;
            rp[g * 2 + j]       = pack_h2(d0, d1);   // default: stays in L2
            rp[(g + 8) * 2 + j] = pack_h2(d2, d3);
        }
    }
}

// ---------------------------------------------------------------------------
// Kernel 4: pool. One warp per bag; 16 contiguous 128B rows (expected L2
// hits); fp32 accumulation per lane slot (m = l>>1, q0-pair j = l&1).
// ---------------------------------------------------------------------------
__global__ void tt_pool_kernel(const int* __restrict__ offsets,
                               float* __restrict__ out, int B) {
    int bag = (int)((blockIdx.x * (size_t)blockDim.x + threadIdx.x) >> 5);
    if (bag >= B) return;
    int l = threadIdx.x & 31;
    int m = l >> 1, j = l & 1;

    int s = offsets[bag], e = offsets[bag + 1];
    float sx = 0.f, sy = 0.f;
    #pragma unroll 4
    for (int n = s; n < e; n++) {
        unsigned u = __ldcs(g_rows + (size_t)n * 32 + l);  // consume-once
        float2 f = __half22float2(*(__half2*)&u);
        sx += f.x;
        sy += f.y;
    }
    float* ob = out + (size_t)bag * 64;
    ob[(2 * j) * 16 + m]     = sx;
    ob[(2 * j + 1) * 16 + m] = sy;
}

// ---------------------------------------------------------------------------
extern "C" void kernel_launch(void* const* d_in, const int* in_sizes, int n_in,
                              void* d_out, int out_size) {
    const int* indices = (const int*)d_in[0];
    const int* offsets = (const int*)d_in[1];
    const float* c0 = (const float*)d_in[2];
    const float* c1 = (const float*)d_in[3];
    const float* c2 = (const float*)d_in[4];

    int nnz = in_sizes[0];
    int B = in_sizes[1] - 1;
    int nnz_per_table = nnz / NT;

    tt_precompute_kernel<<<NT * P1C + NT + 40, 256>>>(c1, c2, c0);
    tt_scatter_kernel<<<(nnz + 255) / 256, 256>>>(indices, nnz, nnz_per_table);
    tt_materialize_kernel<<<(NSLICE + 7) / 8, 256>>>();
    tt_pool_kernel<<<(B + 7) / 8, 256>>>(offsets, (float*)d_out, B);
}